// round 15
// baseline (speedup 1.0000x reference)
#include <cuda_runtime.h>
#include <cuda_fp16.h>
#include <mma.h>
#include <cstdint>

using namespace nvcuda;

#define NN 50000
#define EE 800000
#define HH 128
#define CAP 64             // bucket capacity (deg ~ Binom(800K,1/50K), P(>=64) ~ 1e-14)
#define NPAD 50048         // 391 * 128

#define TILE_M 128
#define MMA_GRID ((NN + TILE_M - 1) / TILE_M)        // 391
#define CP_GRID ((EE / 4 + 255) / 256)               // 782 (count+place, 4 edges/thread)
#define WT_GRID 128                                  // 2*128*128/256

#define LDH 136            // padded smem leading dim (halves)
// A[128][LDH] + Bt[128][LDH] fp16 = 69632 B; C[128][128] fp32 (64 KB) + d[128] reuse it
#define SMEM_BYTES (256 * LDH * 2)
#define D_OFF 65536        // d_sm region (past C); overlaps dead B tail only

// ---------------- scratch (device globals; allocation-free, zero-init) ----------------
__device__ int    g_cnt[NPAD];        // padded: OOB rows read zero; re-zeroed by gather2
__device__ int    g_ccol[NN * CAP];
__device__ __half g_wt[2 * HH * HH];  // fp16 W1^T, W2^T  (wt[n*128+k] = W[k*128+n])
__device__ __half g_xwh[NN * HH];     // layer-1 messages (gather source, read-only in fused)
__device__ __half g_xwh2[NN * HH];    // layer-2 messages (fused kernel output)

__device__ __forceinline__ unsigned pack_h2(float a, float b) {
    __half2 h = __floats2half2_rn(a, b);
    return *reinterpret_cast<unsigned*>(&h);
}

// ---------------- prep: single-pass bucket build || W transposes -> fp16 ----------------

__global__ void __launch_bounds__(256) prep_kernel(
    const float* __restrict__ W1, const float* __restrict__ W2,
    const int4* __restrict__ row4, const int4* __restrict__ col4)
{
    unsigned b = blockIdx.x;
    if (b < CP_GRID) {
        int e = b * 256 + threadIdx.x;
        if (e < EE / 4) {
            int4 r = row4[e];
            int4 c = col4[e];
            g_ccol[r.x * CAP + atomicAdd(&g_cnt[r.x], 1)] = c.x;
            g_ccol[r.y * CAP + atomicAdd(&g_cnt[r.y], 1)] = c.y;
            g_ccol[r.z * CAP + atomicAdd(&g_cnt[r.z], 1)] = c.z;
            g_ccol[r.w * CAP + atomicAdd(&g_cnt[r.w], 1)] = c.w;
        }
    } else {
        int i = (b - CP_GRID) * 256 + threadIdx.x;  // 0..32767
        int w = i >> 14, n = (i >> 7) & 127, k = i & 127;
        const float* W = w ? W2 : W1;
        g_wt[(size_t)w * 16384 + n * 128 + k] = __float2half(W[k * 128 + n]);
    }
}

// ---------------- helpers ----------------

__device__ __forceinline__ void acc_h4(float4& a, uint2 u) {
    __half2 h01 = *reinterpret_cast<__half2*>(&u.x);
    __half2 h23 = *reinterpret_cast<__half2*>(&u.y);
    float2 f01 = __half22float2(h01);
    float2 f23 = __half22float2(h23);
    a.x += f01.x; a.y += f01.y; a.z += f23.x; a.w += f23.y;
}

// warp-wide gather of one row r: acc = xws[r] + sum_c xws[c] (lane owns 4 cols at lo)
__device__ __forceinline__ float4 gather_row(
    const __half* __restrict__ xwh, int r, int cnt, int lo)
{
    const int beg = r * CAP;
    const int end = beg + cnt;
    float4 acc = make_float4(0.f, 0.f, 0.f, 0.f);
    {
        uint2 sv = __ldg((const uint2*)(xwh + (size_t)r * HH + lo));  // self (pre-scaled)
        acc_h4(acc, sv);
    }
    float4 acc2 = make_float4(0.f, 0.f, 0.f, 0.f);
    int i = beg;
    for (; i + 8 <= end; i += 8) {
        int c0 = g_ccol[i + 0], c1 = g_ccol[i + 1], c2 = g_ccol[i + 2], c3 = g_ccol[i + 3];
        int c4 = g_ccol[i + 4], c5 = g_ccol[i + 5], c6 = g_ccol[i + 6], c7 = g_ccol[i + 7];
        uint2 v0 = __ldg((const uint2*)(xwh + (size_t)c0 * HH + lo));
        uint2 v1 = __ldg((const uint2*)(xwh + (size_t)c1 * HH + lo));
        uint2 v2 = __ldg((const uint2*)(xwh + (size_t)c2 * HH + lo));
        uint2 v3 = __ldg((const uint2*)(xwh + (size_t)c3 * HH + lo));
        uint2 v4 = __ldg((const uint2*)(xwh + (size_t)c4 * HH + lo));
        uint2 v5 = __ldg((const uint2*)(xwh + (size_t)c5 * HH + lo));
        uint2 v6 = __ldg((const uint2*)(xwh + (size_t)c6 * HH + lo));
        uint2 v7 = __ldg((const uint2*)(xwh + (size_t)c7 * HH + lo));
        acc_h4(acc,  v0); acc_h4(acc,  v1); acc_h4(acc,  v2); acc_h4(acc,  v3);
        acc_h4(acc2, v4); acc_h4(acc2, v5); acc_h4(acc2, v6); acc_h4(acc2, v7);
    }
    if (i + 4 <= end) {
        int c0 = g_ccol[i + 0], c1 = g_ccol[i + 1], c2 = g_ccol[i + 2], c3 = g_ccol[i + 3];
        uint2 v0 = __ldg((const uint2*)(xwh + (size_t)c0 * HH + lo));
        uint2 v1 = __ldg((const uint2*)(xwh + (size_t)c1 * HH + lo));
        uint2 v2 = __ldg((const uint2*)(xwh + (size_t)c2 * HH + lo));
        uint2 v3 = __ldg((const uint2*)(xwh + (size_t)c3 * HH + lo));
        acc_h4(acc, v0); acc_h4(acc, v1); acc_h4(acc2, v2); acc_h4(acc2, v3);
        i += 4;
    }
    for (; i < end; i++) {
        uint2 v = __ldg((const uint2*)(xwh + (size_t)g_ccol[i] * HH + lo));
        acc_h4(acc2, v);
    }
    acc.x += acc2.x; acc.y += acc2.y; acc.z += acc2.z; acc.w += acc2.w;
    return acc;
}

// ---------------- wmma GEMM core (8 warps, 2x4 frags, col-major Bt) ----------------

__device__ __forceinline__ void mma_core_and_store(
    char* smem, int tid, int row_base, __half* __restrict__ outh)
{
    __half* a_sm = reinterpret_cast<__half*>(smem);
    __half* b_sm = reinterpret_cast<__half*>(smem) + TILE_M * LDH;
    float*  c_sm = reinterpret_cast<float*>(smem);
    float*  d_sm = reinterpret_cast<float*>(smem + D_OFF);

    const int wid = tid >> 5;
    const int wr = wid >> 1, wc = wid & 1;

    wmma::fragment<wmma::accumulator, 16, 16, 16, float> acc[2][4];
#pragma unroll
    for (int i = 0; i < 2; i++)
#pragma unroll
        for (int j = 0; j < 4; j++) wmma::fill_fragment(acc[i][j], 0.0f);

#pragma unroll
    for (int kk = 0; kk < 8; kk++) {
        const int kof = kk * 16;
        wmma::fragment<wmma::matrix_a, 16, 16, 16, __half, wmma::row_major> af[2];
        wmma::fragment<wmma::matrix_b, 16, 16, 16, __half, wmma::col_major> bf[4];
        wmma::load_matrix_sync(af[0], a_sm + (wr * 32 +  0) * LDH + kof, LDH);
        wmma::load_matrix_sync(af[1], a_sm + (wr * 32 + 16) * LDH + kof, LDH);
#pragma unroll
        for (int j = 0; j < 4; j++)
            wmma::load_matrix_sync(bf[j], b_sm + (wc * 64 + j * 16) * LDH + kof, LDH);
#pragma unroll
        for (int i = 0; i < 2; i++)
#pragma unroll
            for (int j = 0; j < 4; j++)
                wmma::mma_sync(acc[i][j], af[i], bf[j], acc[i][j]);
    }

    __syncthreads();  // done reading a_sm/b_sm; c_sm/d_sm reuse the space

#pragma unroll
    for (int i = 0; i < 2; i++)
#pragma unroll
        for (int j = 0; j < 4; j++)
            wmma::store_matrix_sync(c_sm + (wr * 32 + i * 16) * 128 + wc * 64 + j * 16,
                                    acc[i][j], 128, wmma::mem_row_major);
    if (tid < TILE_M)
        d_sm[tid] = rsqrtf((float)g_cnt[row_base + tid] + 1.0f);
    __syncthreads();

    // epilogue: scale row by d_sm[r], fp16 store
#pragma unroll
    for (int i = 0; i < 16; i++) {
        int idx = tid + i * 256;          // 0..4095 float4s
        int r = idx >> 5, c = idx & 31;
        int grow = row_base + r;
        if (grow < NN) {
            float d = d_sm[r];
            float4 v = *reinterpret_cast<float4*>(c_sm + r * 128 + c * 4);
            *reinterpret_cast<uint2*>(outh + (size_t)grow * HH + c * 4) =
                make_uint2(pack_h2(d * v.x, d * v.y), pack_h2(d * v.z, d * v.w));
        }
    }
}

__device__ __forceinline__ void load_bt_tile(const __half* __restrict__ Bt,
                                             __half* b_sm, int tid)
{
#pragma unroll
    for (int i = 0; i < 8; i++) {
        int idx = tid + i * 256;          // 0..2047 uint4s (128 rows x 16 chunks)
        int r = idx >> 4, c = idx & 15;
        *reinterpret_cast<uint4*>(b_sm + r * LDH + c * 8) =
            *reinterpret_cast<const uint4*>(Bt + (size_t)r * HH + c * 8);
    }
}

// ---------------- GEMM layer 1 (fp32 X, fused conversion) ----------------

__global__ void __launch_bounds__(256) gemm1_kernel(
    const float* __restrict__ X, const __half* __restrict__ Bt,
    __half* __restrict__ outh)
{
    extern __shared__ char smem[];
    __half* a_sm = reinterpret_cast<__half*>(smem);
    __half* b_sm = reinterpret_cast<__half*>(smem) + TILE_M * LDH;
    const int tid = threadIdx.x;
    const int row_base = blockIdx.x * TILE_M;

#pragma unroll
    for (int i = 0; i < 16; i++) {
        int idx = tid + i * 256;          // 0..4095 float4s
        int r = idx >> 5, c = idx & 31;
        int grow = row_base + r;
        float4 v = (grow < NN)
            ? __ldg(reinterpret_cast<const float4*>(X + (size_t)grow * HH + c * 4))
            : make_float4(0.f, 0.f, 0.f, 0.f);
        *reinterpret_cast<uint2*>(a_sm + r * LDH + c * 4) =
            make_uint2(pack_h2(v.x, v.y), pack_h2(v.z, v.w));
    }
    load_bt_tile(Bt, b_sm, tid);
    __syncthreads();
    mma_core_and_store(smem, tid, row_base, outh);
}

// ---------------- FUSED: gather layer-1 rows -> h tile in smem -> GEMM layer 2 ----------------
// Reads ONLY g_xwh (stable); writes ONLY g_xwh2 (distinct buffer — no cross-CTA race).

__global__ void __launch_bounds__(256) gather_gemm2_kernel(
    const __half* __restrict__ xwh_in, const float* __restrict__ b1,
    const __half* __restrict__ Bt, __half* __restrict__ outh)
{
    extern __shared__ char smem[];
    __half* a_sm = reinterpret_cast<__half*>(smem);
    __half* b_sm = reinterpret_cast<__half*>(smem) + TILE_M * LDH;
    const int tid = threadIdx.x;
    const int wid = tid >> 5, lane = tid & 31;
    const int row_base = blockIdx.x * TILE_M;
    const int lo = lane * 4;

    load_bt_tile(Bt, b_sm, tid);

    float4 bv = __ldg((const float4*)(b1 + lo));

    // gather phase: warp w handles rows w, w+8, ..., w+120 of the tile
#pragma unroll
    for (int j = 0; j < 16; j++) {
        int r = wid + j * 8;              // tile-local row
        int grow = row_base + r;
        uint2 hrow = make_uint2(0u, 0u);
        if (grow < NN) {
            int cnt = g_cnt[grow];
            float4 acc = gather_row(xwh_in, grow, cnt, lo);
            float d = rsqrtf((float)cnt + 1.0f);
            float hx = fmaxf(fmaf(d, acc.x, bv.x), 0.f);
            float hy = fmaxf(fmaf(d, acc.y, bv.y), 0.f);
            float hz = fmaxf(fmaf(d, acc.z, bv.z), 0.f);
            float hw = fmaxf(fmaf(d, acc.w, bv.w), 0.f);
            hrow = make_uint2(pack_h2(hx, hy), pack_h2(hz, hw));
        }
        *reinterpret_cast<uint2*>(a_sm + r * LDH + lo) = hrow;
    }
    __syncthreads();
    mma_core_and_store(smem, tid, row_base, outh);
}

// ---------------- gather layer 2: out = d_r*(xws2[r] + sum xws2[c]) + b2; zero cnt ----------------

__global__ void __launch_bounds__(256) gather2_kernel(
    const __half* __restrict__ xwh2, const float* __restrict__ bias,
    float* __restrict__ outf)
{
    const int warp = (blockIdx.x * 256 + threadIdx.x) >> 5;
    const int lane = threadIdx.x & 31;
    if (warp >= NN) return;
    const int r = warp;
    const int cnt = g_cnt[r];
    const int lo = lane * 4;
    const float d = rsqrtf((float)cnt + 1.0f);

    float4 acc = gather_row(xwh2, r, cnt, lo);

    float4 bv = __ldg((const float4*)(bias + lo));
    float4 o;
    o.x = fmaf(d, acc.x, bv.x);
    o.y = fmaf(d, acc.y, bv.y);
    o.z = fmaf(d, acc.z, bv.z);
    o.w = fmaf(d, acc.w, bv.w);
    *reinterpret_cast<float4*>(outf + (size_t)r * HH + lo) = o;

    if (lane == 0) g_cnt[r] = 0;   // reset for next graph replay (last consumer)
}

// ---------------- launch ----------------

extern "C" void kernel_launch(void* const* d_in, const int* in_sizes, int n_in,
                              void* d_out, int out_size) {
    const float* x   = (const float*)d_in[0];
    const int* eidx  = (const int*)d_in[1];   // [2, E]
    const float* W1  = (const float*)d_in[2];
    const float* b1  = (const float*)d_in[3];
    const float* W2  = (const float*)d_in[4];
    const float* b2  = (const float*)d_in[5];
    float* out = (float*)d_out;

    const int4* row4 = (const int4*)eidx;
    const int4* col4 = (const int4*)(eidx + EE);

    __half* xwh;  cudaGetSymbolAddress((void**)&xwh,  g_xwh);
    __half* xwh2; cudaGetSymbolAddress((void**)&xwh2, g_xwh2);
    __half* wt;   cudaGetSymbolAddress((void**)&wt,   g_wt);

    cudaFuncSetAttribute(gemm1_kernel,
                         cudaFuncAttributeMaxDynamicSharedMemorySize, SMEM_BYTES);
    cudaFuncSetAttribute(gather_gemm2_kernel,
                         cudaFuncAttributeMaxDynamicSharedMemorySize, SMEM_BYTES);

    const int gather_grid = (NN * 32 + 255) / 256;

    // single-pass bucket build || W transposes  (g_cnt zeroed by prior gather2 / init)
    prep_kernel<<<CP_GRID + WT_GRID, 256>>>(W1, W2, row4, col4);

    // layer 1 GEMM (fp32 X fused conversion, dinv-prescaled epilogue) -> g_xwh
    gemm1_kernel<<<MMA_GRID, 256, SMEM_BYTES>>>(x, wt, xwh);

    // fused: layer-1 aggregate (into smem) + layer-2 GEMM -> g_xwh2 (distinct buffer)
    gather_gemm2_kernel<<<MMA_GRID, 256, SMEM_BYTES>>>(xwh, b1, wt + HH * HH, xwh2);

    // layer-2 aggregate -> final output; resets g_cnt for next replay
    gather2_kernel<<<gather_grid, 256>>>(xwh2, b2, out);
}

// round 16
// speedup vs baseline: 1.3542x; 1.3542x over previous
#include <cuda_runtime.h>
#include <cuda_fp16.h>
#include <mma.h>
#include <cstdint>

using namespace nvcuda;

#define NN 50000
#define EE 800000
#define HH 128
#define CAP 64             // bucket capacity (deg ~ Binom(800K,1/50K), P(>=64) ~ 1e-14)
#define NPAD 50048         // 391 * 128

#define TILE_M 128
#define MMA_GRID ((NN + TILE_M - 1) / TILE_M)        // 391
#define CNT_GRID ((EE / 4 + 255) / 256)              // 782
#define WT_GRID 128                                  // 2*128*128/256
#define PLACE_GRID ((EE / 4 + 255) / 256)            // 782

#define LDH 136            // padded smem leading dim (halves)
// A[128][LDH] + Bt[128][LDH] fp16 = 69632 B; C[128][128] fp32 (64 KB) + d[128] reuse it
#define SMEM_BYTES (256 * LDH * 2)
#define D_OFF 65536        // d_sm region (past C); overlaps dead B tail only

// ---------------- scratch (device globals; allocation-free, zero-init) ----------------
__device__ int           g_cnt[NPAD];   // padded: OOB rows read zero; re-zeroed by gather2
__device__ unsigned char g_rank[EE];
__device__ int           g_ccol[NN * CAP];
__device__ __half        g_hh[NPAD * HH];    // fp16 layer-1 activations (padded rows stay zero)
__device__ __half        g_wt[2 * HH * HH];  // fp16 W1^T, W2^T  (wt[n*128+k] = W[k*128+n])
__device__ __half        g_xwh[NN * HH];     // fp16 dinv-scaled GEMM out (gather source)

__device__ __forceinline__ unsigned pack_h2(float a, float b) {
    __half2 h = __floats2half2_rn(a, b);
    return *reinterpret_cast<unsigned*>(&h);
}

// ---------------- prep: degree count+rank || W transposes -> fp16 ----------------

__global__ void __launch_bounds__(256) prep_kernel(
    const float* __restrict__ W1, const float* __restrict__ W2,
    const int4* __restrict__ row4)
{
    unsigned b = blockIdx.x;
    if (b < CNT_GRID) {
        int e = b * 256 + threadIdx.x;
        if (e < EE / 4) {
            int4 v = row4[e];
            int r0 = atomicAdd(&g_cnt[v.x], 1);
            int r1 = atomicAdd(&g_cnt[v.y], 1);
            int r2 = atomicAdd(&g_cnt[v.z], 1);
            int r3 = atomicAdd(&g_cnt[v.w], 1);
            uchar4 rk = make_uchar4((unsigned char)r0, (unsigned char)r1,
                                    (unsigned char)r2, (unsigned char)r3);
            *reinterpret_cast<uchar4*>(&g_rank[(size_t)e * 4]) = rk;
        }
    } else {
        int i = (b - CNT_GRID) * 256 + threadIdx.x;  // 0..32767
        int w = i >> 14, n = (i >> 7) & 127, k = i & 127;
        const float* W = w ? W2 : W1;
        g_wt[(size_t)w * 16384 + n * 128 + k] = __float2half(W[k * 128 + n]);
    }
}

// ---------------- wmma GEMM core (8 warps, 2x4 frags, col-major Bt) ----------------
// out_scaled[m][n] = rsqrt(cnt[m]+1) * sum_k A[m][k]*W[k][n];  Bt[n][k] -> matrix_b col_major.

__device__ __forceinline__ void mma_core_and_store(
    char* smem, int tid, int row_base, __half* __restrict__ outh)
{
    __half* a_sm = reinterpret_cast<__half*>(smem);
    __half* b_sm = reinterpret_cast<__half*>(smem) + TILE_M * LDH;
    float*  c_sm = reinterpret_cast<float*>(smem);
    float*  d_sm = reinterpret_cast<float*>(smem + D_OFF);

    const int wid = tid >> 5;
    const int wr = wid >> 1, wc = wid & 1;

    wmma::fragment<wmma::accumulator, 16, 16, 16, float> acc[2][4];
#pragma unroll
    for (int i = 0; i < 2; i++)
#pragma unroll
        for (int j = 0; j < 4; j++) wmma::fill_fragment(acc[i][j], 0.0f);

#pragma unroll
    for (int kk = 0; kk < 8; kk++) {
        const int kof = kk * 16;
        wmma::fragment<wmma::matrix_a, 16, 16, 16, __half, wmma::row_major> af[2];
        wmma::fragment<wmma::matrix_b, 16, 16, 16, __half, wmma::col_major> bf[4];
        wmma::load_matrix_sync(af[0], a_sm + (wr * 32 +  0) * LDH + kof, LDH);
        wmma::load_matrix_sync(af[1], a_sm + (wr * 32 + 16) * LDH + kof, LDH);
#pragma unroll
        for (int j = 0; j < 4; j++)
            wmma::load_matrix_sync(bf[j], b_sm + (wc * 64 + j * 16) * LDH + kof, LDH);
#pragma unroll
        for (int i = 0; i < 2; i++)
#pragma unroll
            for (int j = 0; j < 4; j++)
                wmma::mma_sync(acc[i][j], af[i], bf[j], acc[i][j]);
    }

    __syncthreads();  // done reading a_sm/b_sm; c_sm/d_sm reuse the space

#pragma unroll
    for (int i = 0; i < 2; i++)
#pragma unroll
        for (int j = 0; j < 4; j++)
            wmma::store_matrix_sync(c_sm + (wr * 32 + i * 16) * 128 + wc * 64 + j * 16,
                                    acc[i][j], 128, wmma::mem_row_major);
    if (tid < TILE_M)
        d_sm[tid] = rsqrtf((float)g_cnt[row_base + tid] + 1.0f);
    __syncthreads();

    // epilogue: scale row by d_sm[r], fp16 store
#pragma unroll
    for (int i = 0; i < 16; i++) {
        int idx = tid + i * 256;          // 0..4095 float4s
        int r = idx >> 5, c = idx & 31;
        int grow = row_base + r;
        if (grow < NN) {
            float d = d_sm[r];
            float4 v = *reinterpret_cast<float4*>(c_sm + r * 128 + c * 4);
            *reinterpret_cast<uint2*>(outh + (size_t)grow * HH + c * 4) =
                make_uint2(pack_h2(d * v.x, d * v.y), pack_h2(d * v.z, d * v.w));
        }
    }
}

__device__ __forceinline__ void load_bt_tile(const __half* __restrict__ Bt,
                                             __half* b_sm, int tid)
{
#pragma unroll
    for (int i = 0; i < 8; i++) {
        int idx = tid + i * 256;          // 0..2047 uint4s (128 rows x 16 chunks)
        int r = idx >> 4, c = idx & 15;
        *reinterpret_cast<uint4*>(b_sm + r * LDH + c * 8) =
            *reinterpret_cast<const uint4*>(Bt + (size_t)r * HH + c * 8);
    }
}

// ---------------- merged: GEMM layer 1 (fp32 X, fused conv) || bucket place ----------------

__global__ void __launch_bounds__(256) gemm1_place_kernel(
    const float* __restrict__ X, const __half* __restrict__ Bt,
    __half* __restrict__ outh,
    const int4* __restrict__ row4, const int4* __restrict__ col4)
{
    extern __shared__ char smem[];
    unsigned b = blockIdx.x;
    if (b < MMA_GRID) {
        __half* a_sm = reinterpret_cast<__half*>(smem);
        __half* b_sm = reinterpret_cast<__half*>(smem) + TILE_M * LDH;
        const int tid = threadIdx.x;
        const int row_base = b * TILE_M;
#pragma unroll
        for (int i = 0; i < 16; i++) {
            int idx = tid + i * 256;      // 0..4095 float4s
            int r = idx >> 5, c = idx & 31;
            int grow = row_base + r;
            float4 v = (grow < NN)
                ? __ldg(reinterpret_cast<const float4*>(X + (size_t)grow * HH + c * 4))
                : make_float4(0.f, 0.f, 0.f, 0.f);
            *reinterpret_cast<uint2*>(a_sm + r * LDH + c * 4) =
                make_uint2(pack_h2(v.x, v.y), pack_h2(v.z, v.w));
        }
        load_bt_tile(Bt, b_sm, tid);
        __syncthreads();
        mma_core_and_store(smem, tid, row_base, outh);
    } else {
        int e = (b - MMA_GRID) * 256 + threadIdx.x;
        if (e < EE / 4) {
            int4 r = row4[e];
            int4 c = col4[e];
            uchar4 rk = *reinterpret_cast<const uchar4*>(&g_rank[(size_t)e * 4]);
            g_ccol[r.x * CAP + rk.x] = c.x;
            g_ccol[r.y * CAP + rk.y] = c.y;
            g_ccol[r.z * CAP + rk.z] = c.z;
            g_ccol[r.w * CAP + rk.w] = c.w;
        }
    }
}

// ---------------- GEMM layer 2 (fp16 A, padded buffer: no load predicate) ----------------

__global__ void __launch_bounds__(256) gemm2_kernel(
    const __half* __restrict__ A, const __half* __restrict__ Bt,
    __half* __restrict__ outh)
{
    extern __shared__ char smem[];
    __half* a_sm = reinterpret_cast<__half*>(smem);
    __half* b_sm = reinterpret_cast<__half*>(smem) + TILE_M * LDH;
    const int tid = threadIdx.x;
    const int row_base = blockIdx.x * TILE_M;

#pragma unroll
    for (int i = 0; i < 8; i++) {
        int idx = tid + i * 256;          // A: 128 rows x 16 uint4
        int r = idx >> 4, c = idx & 15;
        *reinterpret_cast<uint4*>(a_sm + r * LDH + c * 8) =
            *reinterpret_cast<const uint4*>(A + (size_t)(row_base + r) * HH + c * 8);
    }
    load_bt_tile(Bt, b_sm, tid);
    __syncthreads();
    mma_core_and_store(smem, tid, row_base, outh);
}

// ---------------- gather helpers ----------------

__device__ __forceinline__ void acc_h4(float4& a, uint2 u) {
    __half2 h01 = *reinterpret_cast<__half2*>(&u.x);
    __half2 h23 = *reinterpret_cast<__half2*>(&u.y);
    float2 f01 = __half22float2(h01);
    float2 f23 = __half22float2(h23);
    a.x += f01.x; a.y += f01.y; a.z += f23.x; a.w += f23.y;
}

__device__ __forceinline__ float4 gather_row(
    const __half* __restrict__ xwh, int r, int cnt, int lo)
{
    const int beg = r * CAP;
    const int end = beg + cnt;
    float4 acc = make_float4(0.f, 0.f, 0.f, 0.f);
    {
        uint2 sv = __ldg((const uint2*)(xwh + (size_t)r * HH + lo));  // self (pre-scaled)
        acc_h4(acc, sv);
    }
    float4 acc2 = make_float4(0.f, 0.f, 0.f, 0.f);
    int i = beg;
    for (; i + 8 <= end; i += 8) {
        int c0 = g_ccol[i + 0], c1 = g_ccol[i + 1], c2 = g_ccol[i + 2], c3 = g_ccol[i + 3];
        int c4 = g_ccol[i + 4], c5 = g_ccol[i + 5], c6 = g_ccol[i + 6], c7 = g_ccol[i + 7];
        uint2 v0 = __ldg((const uint2*)(xwh + (size_t)c0 * HH + lo));
        uint2 v1 = __ldg((const uint2*)(xwh + (size_t)c1 * HH + lo));
        uint2 v2 = __ldg((const uint2*)(xwh + (size_t)c2 * HH + lo));
        uint2 v3 = __ldg((const uint2*)(xwh + (size_t)c3 * HH + lo));
        uint2 v4 = __ldg((const uint2*)(xwh + (size_t)c4 * HH + lo));
        uint2 v5 = __ldg((const uint2*)(xwh + (size_t)c5 * HH + lo));
        uint2 v6 = __ldg((const uint2*)(xwh + (size_t)c6 * HH + lo));
        uint2 v7 = __ldg((const uint2*)(xwh + (size_t)c7 * HH + lo));
        acc_h4(acc,  v0); acc_h4(acc,  v1); acc_h4(acc,  v2); acc_h4(acc,  v3);
        acc_h4(acc2, v4); acc_h4(acc2, v5); acc_h4(acc2, v6); acc_h4(acc2, v7);
    }
    if (i + 4 <= end) {
        int c0 = g_ccol[i + 0], c1 = g_ccol[i + 1], c2 = g_ccol[i + 2], c3 = g_ccol[i + 3];
        uint2 v0 = __ldg((const uint2*)(xwh + (size_t)c0 * HH + lo));
        uint2 v1 = __ldg((const uint2*)(xwh + (size_t)c1 * HH + lo));
        uint2 v2 = __ldg((const uint2*)(xwh + (size_t)c2 * HH + lo));
        uint2 v3 = __ldg((const uint2*)(xwh + (size_t)c3 * HH + lo));
        acc_h4(acc, v0); acc_h4(acc, v1); acc_h4(acc2, v2); acc_h4(acc2, v3);
        i += 4;
    }
    for (; i < end; i++) {
        uint2 v = __ldg((const uint2*)(xwh + (size_t)g_ccol[i] * HH + lo));
        acc_h4(acc2, v);
    }
    acc.x += acc2.x; acc.y += acc2.y; acc.z += acc2.z; acc.w += acc2.w;
    return acc;
}

// ---------------- gather 1: h = relu(d_r*(...) + b1) -> fp16 ----------------

__global__ void __launch_bounds__(256) gather1_kernel(
    const __half* __restrict__ xwh, const float* __restrict__ bias,
    __half* __restrict__ outh)
{
    const int warp = (blockIdx.x * 256 + threadIdx.x) >> 5;
    const int lane = threadIdx.x & 31;
    if (warp >= NN) return;
    const int r = warp;
    const int cnt = g_cnt[r];
    const int lo = lane * 4;
    const float d = rsqrtf((float)cnt + 1.0f);

    float4 acc = gather_row(xwh, r, cnt, lo);

    float4 bv = __ldg((const float4*)(bias + lo));
    float ox = fmaxf(fmaf(d, acc.x, bv.x), 0.f);
    float oy = fmaxf(fmaf(d, acc.y, bv.y), 0.f);
    float oz = fmaxf(fmaf(d, acc.z, bv.z), 0.f);
    float ow = fmaxf(fmaf(d, acc.w, bv.w), 0.f);
    *reinterpret_cast<uint2*>(outh + (size_t)r * HH + lo) =
        make_uint2(pack_h2(ox, oy), pack_h2(oz, ow));
}

// ---------------- gather 2: out = d_r*(...) + b2 (fp32); resets g_cnt ----------------

__global__ void __launch_bounds__(256) gather2_kernel(
    const __half* __restrict__ xwh, const float* __restrict__ bias,
    float* __restrict__ outf)
{
    const int warp = (blockIdx.x * 256 + threadIdx.x) >> 5;
    const int lane = threadIdx.x & 31;
    if (warp >= NN) return;
    const int r = warp;
    const int cnt = g_cnt[r];
    const int lo = lane * 4;
    const float d = rsqrtf((float)cnt + 1.0f);

    float4 acc = gather_row(xwh, r, cnt, lo);

    float4 bv = __ldg((const float4*)(bias + lo));
    float4 o;
    o.x = fmaf(d, acc.x, bv.x);
    o.y = fmaf(d, acc.y, bv.y);
    o.z = fmaf(d, acc.z, bv.z);
    o.w = fmaf(d, acc.w, bv.w);
    *reinterpret_cast<float4*>(outf + (size_t)r * HH + lo) = o;

    if (lane == 0) g_cnt[r] = 0;   // reset for next graph replay (last consumer)
}

// ---------------- launch ----------------

extern "C" void kernel_launch(void* const* d_in, const int* in_sizes, int n_in,
                              void* d_out, int out_size) {
    const float* x   = (const float*)d_in[0];
    const int* eidx  = (const int*)d_in[1];   // [2, E]
    const float* W1  = (const float*)d_in[2];
    const float* b1  = (const float*)d_in[3];
    const float* W2  = (const float*)d_in[4];
    const float* b2  = (const float*)d_in[5];
    float* out = (float*)d_out;

    const int4* row4 = (const int4*)eidx;
    const int4* col4 = (const int4*)(eidx + EE);

    __half* xwh; cudaGetSymbolAddress((void**)&xwh, g_xwh);
    __half* hh;  cudaGetSymbolAddress((void**)&hh,  g_hh);
    __half* wt;  cudaGetSymbolAddress((void**)&wt,  g_wt);

    cudaFuncSetAttribute(gemm1_place_kernel,
                         cudaFuncAttributeMaxDynamicSharedMemorySize, SMEM_BYTES);
    cudaFuncSetAttribute(gemm2_kernel,
                         cudaFuncAttributeMaxDynamicSharedMemorySize, SMEM_BYTES);

    const int gather_grid = (NN * 32 + 255) / 256;

    // degree count+rank || W transposes  (g_cnt zeroed by prior gather2 / zero-init)
    prep_kernel<<<CNT_GRID + WT_GRID, 256>>>(W1, W2, row4);

    // GEMM1 (fp32 X fused conversion, dinv-prescaled epilogue) || bucket place
    gemm1_place_kernel<<<MMA_GRID + PLACE_GRID, 256, SMEM_BYTES>>>(
        x, wt, xwh, row4, col4);

    // layer 1 aggregate -> fp16 activations (full-occupancy standalone gather)
    gather1_kernel<<<gather_grid, 256>>>(xwh, b1, hh);

    // layer 2
    gemm2_kernel<<<MMA_GRID, 256, SMEM_BYTES>>>(hh, wt + HH * HH, xwh);
    gather2_kernel<<<gather_grid, 256>>>(xwh, b2, out);
}

// round 17
// speedup vs baseline: 1.3711x; 1.0125x over previous
#include <cuda_runtime.h>
#include <cuda_fp16.h>
#include <mma.h>
#include <cstdint>

using namespace nvcuda;

#define NN 50000
#define EE 800000
#define HH 128
#define CAP 64             // bucket capacity (deg ~ Binom(800K,1/50K), P(>=64) ~ 1e-14)
#define NPAD 50048         // 391 * 128

#define TILE_M 128
#define NT 512             // 16 warps per GEMM CTA
#define MMA_GRID ((NN + TILE_M - 1) / TILE_M)        // 391
#define CNT_GRID ((EE / 4 + 255) / 256)              // 782
#define WT_GRID 128                                  // 2*128*128/256
#define PLACE_GRID ((EE / 4 + NT - 1) / NT)          // 391

#define LDH 136            // padded smem leading dim (halves)
// A[128][LDH] + Bt[128][LDH] fp16 = 69632 B; C[128][128] fp32 (64 KB) + d[128] reuse it
#define SMEM_BYTES (256 * LDH * 2)
#define D_OFF 65536        // d_sm region (past C); overlaps dead B tail only

// ---------------- scratch (device globals; allocation-free, zero-init) ----------------
__device__ int           g_cnt[NPAD];   // padded: OOB rows read zero; re-zeroed by gather2
__device__ unsigned char g_rank[EE];
__device__ int           g_ccol[NN * CAP];
__device__ __half        g_hh[NPAD * HH];    // fp16 layer-1 activations (padded rows stay zero)
__device__ __half        g_wt[2 * HH * HH];  // fp16 W1^T, W2^T  (wt[n*128+k] = W[k*128+n])
__device__ __half        g_xwh[NN * HH];     // fp16 dinv-scaled GEMM out (gather source)

__device__ __forceinline__ unsigned pack_h2(float a, float b) {
    __half2 h = __floats2half2_rn(a, b);
    return *reinterpret_cast<unsigned*>(&h);
}

// ---------------- prep: degree count+rank || W transposes -> fp16 ----------------

__global__ void __launch_bounds__(256) prep_kernel(
    const float* __restrict__ W1, const float* __restrict__ W2,
    const int4* __restrict__ row4)
{
    unsigned b = blockIdx.x;
    if (b < CNT_GRID) {
        int e = b * 256 + threadIdx.x;
        if (e < EE / 4) {
            int4 v = row4[e];
            int r0 = atomicAdd(&g_cnt[v.x], 1);
            int r1 = atomicAdd(&g_cnt[v.y], 1);
            int r2 = atomicAdd(&g_cnt[v.z], 1);
            int r3 = atomicAdd(&g_cnt[v.w], 1);
            uchar4 rk = make_uchar4((unsigned char)r0, (unsigned char)r1,
                                    (unsigned char)r2, (unsigned char)r3);
            *reinterpret_cast<uchar4*>(&g_rank[(size_t)e * 4]) = rk;
        }
    } else {
        int i = (b - CNT_GRID) * 256 + threadIdx.x;  // 0..32767
        int w = i >> 14, n = (i >> 7) & 127, k = i & 127;
        const float* W = w ? W2 : W1;
        g_wt[(size_t)w * 16384 + n * 128 + k] = __float2half(W[k * 128 + n]);
    }
}

// ---------------- wmma GEMM core (16 warps, 1x4 frags, col-major Bt) ----------------
// warp tile: rows wr*16 (wr = wid>>1), cols wc*64 (wc = wid&1).
// out_scaled[m][n] = rsqrt(cnt[m]+1) * sum_k A[m][k]*W[k][n].

__device__ __forceinline__ void mma_core_and_store(
    char* smem, int tid, int row_base, __half* __restrict__ outh)
{
    __half* a_sm = reinterpret_cast<__half*>(smem);
    __half* b_sm = reinterpret_cast<__half*>(smem) + TILE_M * LDH;
    float*  c_sm = reinterpret_cast<float*>(smem);
    float*  d_sm = reinterpret_cast<float*>(smem + D_OFF);

    const int wid = tid >> 5;
    const int wr = wid >> 1, wc = wid & 1;

    wmma::fragment<wmma::accumulator, 16, 16, 16, float> acc[4];
#pragma unroll
    for (int j = 0; j < 4; j++) wmma::fill_fragment(acc[j], 0.0f);

#pragma unroll
    for (int kk = 0; kk < 8; kk++) {
        const int kof = kk * 16;
        wmma::fragment<wmma::matrix_a, 16, 16, 16, __half, wmma::row_major> af;
        wmma::fragment<wmma::matrix_b, 16, 16, 16, __half, wmma::col_major> bf[4];
        wmma::load_matrix_sync(af, a_sm + (wr * 16) * LDH + kof, LDH);
#pragma unroll
        for (int j = 0; j < 4; j++)
            wmma::load_matrix_sync(bf[j], b_sm + (wc * 64 + j * 16) * LDH + kof, LDH);
#pragma unroll
        for (int j = 0; j < 4; j++)
            wmma::mma_sync(acc[j], af, bf[j], acc[j]);
    }

    __syncthreads();  // done reading a_sm/b_sm; c_sm/d_sm reuse the space

#pragma unroll
    for (int j = 0; j < 4; j++)
        wmma::store_matrix_sync(c_sm + (wr * 16) * 128 + wc * 64 + j * 16,
                                acc[j], 128, wmma::mem_row_major);
    if (tid < TILE_M)
        d_sm[tid] = rsqrtf((float)g_cnt[row_base + tid] + 1.0f);
    __syncthreads();

    // epilogue: scale row by d_sm[r], fp16 store
#pragma unroll
    for (int i = 0; i < 8; i++) {
        int idx = tid + i * NT;           // 0..4095 float4s
        int r = idx >> 5, c = idx & 31;
        int grow = row_base + r;
        if (grow < NN) {
            float d = d_sm[r];
            float4 v = *reinterpret_cast<float4*>(c_sm + r * 128 + c * 4);
            *reinterpret_cast<uint2*>(outh + (size_t)grow * HH + c * 4) =
                make_uint2(pack_h2(d * v.x, d * v.y), pack_h2(d * v.z, d * v.w));
        }
    }
}

__device__ __forceinline__ void load_bt_tile(const __half* __restrict__ Bt,
                                             __half* b_sm, int tid)
{
#pragma unroll
    for (int i = 0; i < 4; i++) {
        int idx = tid + i * NT;           // 0..2047 uint4s (128 rows x 16 chunks)
        int r = idx >> 4, c = idx & 15;
        *reinterpret_cast<uint4*>(b_sm + r * LDH + c * 8) =
            *reinterpret_cast<const uint4*>(Bt + (size_t)r * HH + c * 8);
    }
}

// ---------------- merged: GEMM layer 1 (fp32 X, fused conv) || bucket place ----------------

__global__ void __launch_bounds__(NT) gemm1_place_kernel(
    const float* __restrict__ X, const __half* __restrict__ Bt,
    __half* __restrict__ outh,
    const int4* __restrict__ row4, const int4* __restrict__ col4)
{
    extern __shared__ char smem[];
    unsigned b = blockIdx.x;
    if (b < MMA_GRID) {
        __half* a_sm = reinterpret_cast<__half*>(smem);
        __half* b_sm = reinterpret_cast<__half*>(smem) + TILE_M * LDH;
        const int tid = threadIdx.x;
        const int row_base = b * TILE_M;
#pragma unroll
        for (int i = 0; i < 8; i++) {
            int idx = tid + i * NT;       // 0..4095 float4s
            int r = idx >> 5, c = idx & 31;
            int grow = row_base + r;
            float4 v = (grow < NN)
                ? __ldg(reinterpret_cast<const float4*>(X + (size_t)grow * HH + c * 4))
                : make_float4(0.f, 0.f, 0.f, 0.f);
            *reinterpret_cast<uint2*>(a_sm + r * LDH + c * 4) =
                make_uint2(pack_h2(v.x, v.y), pack_h2(v.z, v.w));
        }
        load_bt_tile(Bt, b_sm, tid);
        __syncthreads();
        mma_core_and_store(smem, tid, row_base, outh);
    } else {
        int e = (b - MMA_GRID) * NT + threadIdx.x;
        if (e < EE / 4) {
            int4 r = row4[e];
            int4 c = col4[e];
            uchar4 rk = *reinterpret_cast<const uchar4*>(&g_rank[(size_t)e * 4]);
            g_ccol[r.x * CAP + rk.x] = c.x;
            g_ccol[r.y * CAP + rk.y] = c.y;
            g_ccol[r.z * CAP + rk.z] = c.z;
            g_ccol[r.w * CAP + rk.w] = c.w;
        }
    }
}

// ---------------- GEMM layer 2 (fp16 A, padded buffer: no load predicate) ----------------

__global__ void __launch_bounds__(NT) gemm2_kernel(
    const __half* __restrict__ A, const __half* __restrict__ Bt,
    __half* __restrict__ outh)
{
    extern __shared__ char smem[];
    __half* a_sm = reinterpret_cast<__half*>(smem);
    __half* b_sm = reinterpret_cast<__half*>(smem) + TILE_M * LDH;
    const int tid = threadIdx.x;
    const int row_base = blockIdx.x * TILE_M;

#pragma unroll
    for (int i = 0; i < 4; i++) {
        int idx = tid + i * NT;           // A: 128 rows x 16 uint4
        int r = idx >> 4, c = idx & 15;
        *reinterpret_cast<uint4*>(a_sm + r * LDH + c * 8) =
            *reinterpret_cast<const uint4*>(A + (size_t)(row_base + r) * HH + c * 8);
    }
    load_bt_tile(Bt, b_sm, tid);
    __syncthreads();
    mma_core_and_store(smem, tid, row_base, outh);
}

// ---------------- gather helpers ----------------

__device__ __forceinline__ void acc_h4(float4& a, uint2 u) {
    __half2 h01 = *reinterpret_cast<__half2*>(&u.x);
    __half2 h23 = *reinterpret_cast<__half2*>(&u.y);
    float2 f01 = __half22float2(h01);
    float2 f23 = __half22float2(h23);
    a.x += f01.x; a.y += f01.y; a.z += f23.x; a.w += f23.y;
}

__device__ __forceinline__ float4 gather_row(
    const __half* __restrict__ xwh, int r, int cnt, int lo)
{
    const int beg = r * CAP;
    const int end = beg + cnt;
    float4 acc = make_float4(0.f, 0.f, 0.f, 0.f);
    {
        uint2 sv = __ldg((const uint2*)(xwh + (size_t)r * HH + lo));  // self (pre-scaled)
        acc_h4(acc, sv);
    }
    float4 acc2 = make_float4(0.f, 0.f, 0.f, 0.f);
    int i = beg;
    for (; i + 8 <= end; i += 8) {
        int c0 = g_ccol[i + 0], c1 = g_ccol[i + 1], c2 = g_ccol[i + 2], c3 = g_ccol[i + 3];
        int c4 = g_ccol[i + 4], c5 = g_ccol[i + 5], c6 = g_ccol[i + 6], c7 = g_ccol[i + 7];
        uint2 v0 = __ldg((const uint2*)(xwh + (size_t)c0 * HH + lo));
        uint2 v1 = __ldg((const uint2*)(xwh + (size_t)c1 * HH + lo));
        uint2 v2 = __ldg((const uint2*)(xwh + (size_t)c2 * HH + lo));
        uint2 v3 = __ldg((const uint2*)(xwh + (size_t)c3 * HH + lo));
        uint2 v4 = __ldg((const uint2*)(xwh + (size_t)c4 * HH + lo));
        uint2 v5 = __ldg((const uint2*)(xwh + (size_t)c5 * HH + lo));
        uint2 v6 = __ldg((const uint2*)(xwh + (size_t)c6 * HH + lo));
        uint2 v7 = __ldg((const uint2*)(xwh + (size_t)c7 * HH + lo));
        acc_h4(acc,  v0); acc_h4(acc,  v1); acc_h4(acc,  v2); acc_h4(acc,  v3);
        acc_h4(acc2, v4); acc_h4(acc2, v5); acc_h4(acc2, v6); acc_h4(acc2, v7);
    }
    if (i + 4 <= end) {
        int c0 = g_ccol[i + 0], c1 = g_ccol[i + 1], c2 = g_ccol[i + 2], c3 = g_ccol[i + 3];
        uint2 v0 = __ldg((const uint2*)(xwh + (size_t)c0 * HH + lo));
        uint2 v1 = __ldg((const uint2*)(xwh + (size_t)c1 * HH + lo));
        uint2 v2 = __ldg((const uint2*)(xwh + (size_t)c2 * HH + lo));
        uint2 v3 = __ldg((const uint2*)(xwh + (size_t)c3 * HH + lo));
        acc_h4(acc, v0); acc_h4(acc, v1); acc_h4(acc2, v2); acc_h4(acc2, v3);
        i += 4;
    }
    for (; i < end; i++) {
        uint2 v = __ldg((const uint2*)(xwh + (size_t)g_ccol[i] * HH + lo));
        acc_h4(acc2, v);
    }
    acc.x += acc2.x; acc.y += acc2.y; acc.z += acc2.z; acc.w += acc2.w;
    return acc;
}

// ---------------- gather 1: h = relu(d_r*(...) + b1) -> fp16 ----------------

__global__ void __launch_bounds__(256) gather1_kernel(
    const __half* __restrict__ xwh, const float* __restrict__ bias,
    __half* __restrict__ outh)
{
    const int warp = (blockIdx.x * 256 + threadIdx.x) >> 5;
    const int lane = threadIdx.x & 31;
    if (warp >= NN) return;
    const int r = warp;
    const int cnt = g_cnt[r];
    const int lo = lane * 4;
    const float d = rsqrtf((float)cnt + 1.0f);

    float4 acc = gather_row(xwh, r, cnt, lo);

    float4 bv = __ldg((const float4*)(bias + lo));
    float ox = fmaxf(fmaf(d, acc.x, bv.x), 0.f);
    float oy = fmaxf(fmaf(d, acc.y, bv.y), 0.f);
    float oz = fmaxf(fmaf(d, acc.z, bv.z), 0.f);
    float ow = fmaxf(fmaf(d, acc.w, bv.w), 0.f);
    *reinterpret_cast<uint2*>(outh + (size_t)r * HH + lo) =
        make_uint2(pack_h2(ox, oy), pack_h2(oz, ow));
}

// ---------------- gather 2: out = d_r*(...) + b2 (fp32); resets g_cnt ----------------

__global__ void __launch_bounds__(256) gather2_kernel(
    const __half* __restrict__ xwh, const float* __restrict__ bias,
    float* __restrict__ outf)
{
    const int warp = (blockIdx.x * 256 + threadIdx.x) >> 5;
    const int lane = threadIdx.x & 31;
    if (warp >= NN) return;
    const int r = warp;
    const int cnt = g_cnt[r];
    const int lo = lane * 4;
    const float d = rsqrtf((float)cnt + 1.0f);

    float4 acc = gather_row(xwh, r, cnt, lo);

    float4 bv = __ldg((const float4*)(bias + lo));
    float4 o;
    o.x = fmaf(d, acc.x, bv.x);
    o.y = fmaf(d, acc.y, bv.y);
    o.z = fmaf(d, acc.z, bv.z);
    o.w = fmaf(d, acc.w, bv.w);
    *reinterpret_cast<float4*>(outf + (size_t)r * HH + lo) = o;

    if (lane == 0) g_cnt[r] = 0;   // reset for next graph replay (last consumer)
}

// ---------------- launch ----------------

extern "C" void kernel_launch(void* const* d_in, const int* in_sizes, int n_in,
                              void* d_out, int out_size) {
    const float* x   = (const float*)d_in[0];
    const int* eidx  = (const int*)d_in[1];   // [2, E]
    const float* W1  = (const float*)d_in[2];
    const float* b1  = (const float*)d_in[3];
    const float* W2  = (const float*)d_in[4];
    const float* b2  = (const float*)d_in[5];
    float* out = (float*)d_out;

    const int4* row4 = (const int4*)eidx;
    const int4* col4 = (const int4*)(eidx + EE);

    __half* xwh; cudaGetSymbolAddress((void**)&xwh, g_xwh);
    __half* hh;  cudaGetSymbolAddress((void**)&hh,  g_hh);
    __half* wt;  cudaGetSymbolAddress((void**)&wt,  g_wt);

    cudaFuncSetAttribute(gemm1_place_kernel,
                         cudaFuncAttributeMaxDynamicSharedMemorySize, SMEM_BYTES);
    cudaFuncSetAttribute(gemm2_kernel,
                         cudaFuncAttributeMaxDynamicSharedMemorySize, SMEM_BYTES);

    const int gather_grid = (NN * 32 + 255) / 256;

    // degree count+rank || W transposes  (g_cnt zeroed by prior gather2 / zero-init)
    prep_kernel<<<CNT_GRID + WT_GRID, 256>>>(W1, W2, row4);

    // GEMM1 (fp32 X fused conversion, dinv-prescaled epilogue) || bucket place
    gemm1_place_kernel<<<MMA_GRID + PLACE_GRID, NT, SMEM_BYTES>>>(
        x, wt, xwh, row4, col4);

    // layer 1 aggregate -> fp16 activations
    gather1_kernel<<<gather_grid, 256>>>(xwh, b1, hh);

    // layer 2
    gemm2_kernel<<<MMA_GRID, NT, SMEM_BYTES>>>(hh, wt + HH * HH, xwh);
    gather2_kernel<<<gather_grid, 256>>>(xwh, b2, out);
}